// round 8
// baseline (speedup 1.0000x reference)
#include <cuda_runtime.h>
#include <cuda_bf16.h>
#include <math.h>
#include <cstdint>

// Problem constants (GCNAggregator): B=4096, K=32, U=32768, V=100000, D=128
#define GCN_B 4096
#define GCN_K 32
#define GCN_U 32768
#define GCN_D 128

#define AGG_ROWS 4                         // warps (rows) per aggregate block
#define CHUNK 16                           // neighbors per stage chunk
#define STAGE_BYTES (2 * AGG_ROWS * CHUNK * 512)      // 64KB double-buffered stage
#define SMEM_TOTAL (STAGE_BYTES + AGG_ROWS * 32 * 8)  // + (off,w) table

// Scratch (no cudaMalloc allowed)
__device__ int      g_col_deg[GCN_U];
__device__ unsigned g_row_mask[GCN_B];  // bit k set = k-th entry is first occurrence in its row

// ---------------------------------------------------------------------------
// Kernel 1: per-row dedupe (one warp per row) + column degree accumulation
// ---------------------------------------------------------------------------
__global__ void dedupe_degree_kernel(const int* __restrict__ neigh_cols) {
    int warp_in_block = threadIdx.x >> 5;
    int lane = threadIdx.x & 31;
    int b = blockIdx.x * (blockDim.x >> 5) + warp_in_block;

    int c = neigh_cols[b * GCN_K + lane];

    bool first = true;
    #pragma unroll
    for (int j = 0; j < GCN_K; j++) {
        int cj = __shfl_sync(0xFFFFFFFFu, c, j);
        if (j < lane && cj == c) first = false;
    }

    unsigned mask = __ballot_sync(0xFFFFFFFFu, first);
    if (lane == 0) g_row_mask[b] = mask;
    if (first) atomicAdd(&g_col_deg[c], 1);   // spread addresses -> cheap
}

// ---------------------------------------------------------------------------
// Kernel 2: aggregation via cp.async (LDGSTS) staging.
// One warp per row. Each neighbor row (512B) is copied by one warp-level
// cp.async.cg (16B/lane) into a double-buffered smem stage; the async copy
// engine has no observed depth cap, bypassing the per-SM outstanding-LDG
// limit that capped all LDG variants at ~25% L2. Each lane later reads back
// exactly the bytes it copied -> per-lane self-consistency, no syncwarp in
// the mainloop. Duplicates carry w=0 -> branch-free.
// ---------------------------------------------------------------------------
__global__ void __launch_bounds__(32 * AGG_ROWS)
aggregate_kernel(const int* __restrict__ neigh_cols,
                 const int* __restrict__ unique_ids,
                 const float4* __restrict__ embed_table4,  // [V, 32] float4
                 float4* __restrict__ out4) {              // [B, 32] float4
    extern __shared__ char smem[];
    float4* s_stage = reinterpret_cast<float4*>(smem);                  // [2][AGG_ROWS][CHUNK][32]
    int2*   s_wo    = reinterpret_cast<int2*>(smem + STAGE_BYTES);      // [AGG_ROWS][32]

    const int warp = threadIdx.x >> 5;
    const int lane = threadIdx.x & 31;
    const int b    = blockIdx.x * AGG_ROWS + warp;

    // ---- prologue: per-lane (offset, weight) -> smem (warp-private region) ----
    const unsigned mask = g_row_mask[b];
    {
        int c = neigh_cols[b * GCN_K + lane];
        bool first = (mask >> lane) & 1u;
        float w = 0.0f;
        if (first) {
            int deg = __ldg(&g_col_deg[c]);       // >= 1 for first occurrences
            w = rsqrtf((float)deg);
        }
        w *= rsqrtf((float)__popc(mask));         // fold row scale into lane weight
        int off4 = __ldg(&unique_ids[c]) * (GCN_D / 4);
        s_wo[warp * 32 + lane] = make_int2(off4, __float_as_int(w));
    }
    __syncwarp();

    const unsigned int stage_u32 =
        (unsigned int)__cvta_generic_to_shared(s_stage);

    // stage slot address for (buf, k, lane) within this warp's slice
    auto slot = [&](int buf, int k) -> unsigned int {
        return stage_u32 + (unsigned int)((((buf * AGG_ROWS + warp) * CHUNK + k) * 32 + lane) * 16);
    };

    // ---- issue BOTH chunks: 32 cp.async in flight per warp ----
    #pragma unroll
    for (int k = 0; k < CHUNK; k++) {
        const float4* src = embed_table4 + s_wo[warp * 32 + k].x + lane;
        asm volatile("cp.async.cg.shared.global [%0], [%1], 16;"
                     :: "r"(slot(0, k)), "l"(src));
    }
    asm volatile("cp.async.commit_group;");
    #pragma unroll
    for (int k = 0; k < CHUNK; k++) {
        const float4* src = embed_table4 + s_wo[warp * 32 + CHUNK + k].x + lane;
        asm volatile("cp.async.cg.shared.global [%0], [%1], 16;"
                     :: "r"(slot(1, k)), "l"(src));
    }
    asm volatile("cp.async.commit_group;");

    // ---- chunk 0 ready -> FMA while chunk 1 is still in flight ----
    asm volatile("cp.async.wait_group 1;" ::: "memory");
    float4 acc = make_float4(0.f, 0.f, 0.f, 0.f);
    #pragma unroll
    for (int k = 0; k < CHUNK; k++) {
        float  w = __int_as_float(s_wo[warp * 32 + k].y);
        float4 v = s_stage[((0 * AGG_ROWS + warp) * CHUNK + k) * 32 + lane];
        acc.x = fmaf(w, v.x, acc.x);
        acc.y = fmaf(w, v.y, acc.y);
        acc.z = fmaf(w, v.z, acc.z);
        acc.w = fmaf(w, v.w, acc.w);
    }

    // ---- chunk 1 ----
    asm volatile("cp.async.wait_group 0;" ::: "memory");
    #pragma unroll
    for (int k = 0; k < CHUNK; k++) {
        float  w = __int_as_float(s_wo[warp * 32 + CHUNK + k].y);
        float4 v = s_stage[((1 * AGG_ROWS + warp) * CHUNK + k) * 32 + lane];
        acc.x = fmaf(w, v.x, acc.x);
        acc.y = fmaf(w, v.y, acc.y);
        acc.z = fmaf(w, v.z, acc.z);
        acc.w = fmaf(w, v.w, acc.w);
    }

    out4[b * (GCN_D / 4) + lane] = acc;
}

// ---------------------------------------------------------------------------
extern "C" void kernel_launch(void* const* d_in, const int* in_sizes, int n_in,
                              void* d_out, int out_size) {
    const int*    neigh_cols   = (const int*)d_in[0];
    const int*    unique_ids   = (const int*)d_in[1];
    const float4* embed_table4 = (const float4*)d_in[2];
    float4*       out4         = (float4*)d_out;

    // Opt in to >48KB dynamic smem (host-side attribute, idempotent, not a stream op).
    static bool attr_done = false;
    if (!attr_done) {
        cudaFuncSetAttribute(aggregate_kernel,
                             cudaFuncAttributeMaxDynamicSharedMemorySize, SMEM_TOTAL);
        attr_done = true;
    }

    // Zero column degrees via a graph memset node (no dedicated kernel launch).
    void* col_deg_ptr = nullptr;
    cudaGetSymbolAddress(&col_deg_ptr, g_col_deg);
    cudaMemsetAsync(col_deg_ptr, 0, GCN_U * sizeof(int));

    dedupe_degree_kernel<<<GCN_B / 8, 256>>>(neigh_cols);
    aggregate_kernel<<<GCN_B / AGG_ROWS, 32 * AGG_ROWS, SMEM_TOTAL>>>(
        neigh_cols, unique_ids, embed_table4, out4);
}

// round 9
// speedup vs baseline: 1.1214x; 1.1214x over previous
#include <cuda_runtime.h>
#include <cuda_bf16.h>
#include <math.h>
#include <cstdint>

// Problem constants (GCNAggregator): B=4096, K=32, U=32768, V=100000, D=128
#define GCN_B 4096
#define GCN_K 32
#define GCN_U 32768
#define GCN_D 128

#define AGG_ROWS 4           // warps per aggregate block (1 row per warp)
#define NCHUNK 8             // neighbors per staged chunk (512B each)
#define CHUNKS (GCN_K / NCHUNK)   // 4
#define CHUNK_BYTES (NCHUNK * 512)

// Scratch (no cudaMalloc allowed)
__device__ int      g_col_deg[GCN_U];
__device__ unsigned g_row_mask[GCN_B];  // bit k set = k-th entry is first occurrence in its row

// ---------------------------------------------------------------------------
// Kernel 1: per-row dedupe (one warp per row) + column degree accumulation
// ---------------------------------------------------------------------------
__global__ void dedupe_degree_kernel(const int* __restrict__ neigh_cols) {
    int warp_in_block = threadIdx.x >> 5;
    int lane = threadIdx.x & 31;
    int b = blockIdx.x * (blockDim.x >> 5) + warp_in_block;

    int c = neigh_cols[b * GCN_K + lane];

    bool first = true;
    #pragma unroll
    for (int j = 0; j < GCN_K; j++) {
        int cj = __shfl_sync(0xFFFFFFFFu, c, j);
        if (j < lane && cj == c) first = false;
    }

    unsigned mask = __ballot_sync(0xFFFFFFFFu, first);
    if (lane == 0) g_row_mask[b] = mask;
    if (first) atomicAdd(&g_col_deg[c], 1);   // spread addresses -> cheap
}

// ---------------------------------------------------------------------------
// mbarrier helpers
// ---------------------------------------------------------------------------
__device__ __forceinline__ void mbar_init(unsigned mbar, unsigned count) {
    asm volatile("mbarrier.init.shared.b64 [%0], %1;" :: "r"(mbar), "r"(count) : "memory");
}
__device__ __forceinline__ void mbar_expect_tx(unsigned mbar, unsigned bytes) {
    asm volatile("mbarrier.arrive.expect_tx.shared.b64 _, [%0], %1;"
                 :: "r"(mbar), "r"(bytes) : "memory");
}
__device__ __forceinline__ void mbar_wait(unsigned mbar, unsigned parity) {
    asm volatile(
        "{\n\t"
        ".reg .pred P;\n\t"
        "WAIT_%=:\n\t"
        "mbarrier.try_wait.parity.acquire.cta.shared::cta.b64 P, [%0], %1, 0x989680;\n\t"
        "@P bra.uni DONE_%=;\n\t"
        "bra.uni WAIT_%=;\n\t"
        "DONE_%=:\n\t"
        "}"
        :: "r"(mbar), "r"(parity) : "memory");
}

// ---------------------------------------------------------------------------
// Kernel 2: aggregation via cp.async.bulk (UBLKCP) sparse row gather.
// The bulk-copy engine bypasses the per-SM L1tex wavefront queue that capped
// every LDG/LDGSTS variant at ~1.2TB/s DRAM pull. One warp per row; 4 chunks
// of 8 neighbors, double-buffered 4KB stages, mbarrier complete_tx per chunk.
// ---------------------------------------------------------------------------
__global__ void __launch_bounds__(32 * AGG_ROWS)
aggregate_kernel(const int* __restrict__ neigh_cols,
                 const int* __restrict__ unique_ids,
                 const float4* __restrict__ embed_table4,  // [V, 32] float4
                 float4* __restrict__ out4) {              // [B, 32] float4
    __shared__ float4             s_stage[AGG_ROWS][2][NCHUNK][32];  // 32KB
    __shared__ int2               s_wo[AGG_ROWS][32];
    __shared__ alignas(8) uint64_t s_mbar[AGG_ROWS][2];

    const int tid  = threadIdx.x;
    const int warp = tid >> 5;
    const int lane = tid & 31;
    const int b    = blockIdx.x * AGG_ROWS + warp;

    if (tid == 0) {
        #pragma unroll
        for (int r = 0; r < AGG_ROWS; r++)
            #pragma unroll
            for (int j = 0; j < 2; j++)
                mbar_init((unsigned)__cvta_generic_to_shared(&s_mbar[r][j]), 1);
        asm volatile("fence.proxy.async.shared::cta;" ::: "memory");
    }

    // ---- prologue: per-lane (offset, weight) -> smem (warp-private region) ----
    const unsigned mask = g_row_mask[b];
    {
        int c = neigh_cols[b * GCN_K + lane];
        bool first = (mask >> lane) & 1u;
        float w = 0.0f;
        if (first) {
            int deg = __ldg(&g_col_deg[c]);       // >= 1 for first occurrences
            w = rsqrtf((float)deg);
        }
        w *= rsqrtf((float)__popc(mask));         // fold row scale into lane weight
        int off4 = __ldg(&unique_ids[c]) * (GCN_D / 4);
        s_wo[warp][lane] = make_int2(off4, __float_as_int(w));
    }
    __syncthreads();                               // covers mbar init + s_wo

    const unsigned mbar_base = (unsigned)__cvta_generic_to_shared(&s_mbar[warp][0]);
    const unsigned stage_base = (unsigned)__cvta_generic_to_shared(&s_stage[warp][0][0][0]);

    // issue chunk c into buffer c&1: lane 0 arms the barrier, lanes 0..7 each
    // copy one 512B neighbor row via the bulk async engine.
    auto issue_chunk = [&](int c) {
        int buf = c & 1;
        if (lane == 0) mbar_expect_tx(mbar_base + buf * 8, CHUNK_BYTES);
        if (lane < NCHUNK) {
            const float4* src = embed_table4 + s_wo[warp][c * NCHUNK + lane].x;
            unsigned dst = stage_base + (unsigned)((buf * NCHUNK + lane) * 512);
            asm volatile(
                "cp.async.bulk.shared::cluster.global.mbarrier::complete_tx::bytes "
                "[%0], [%1], %2, [%3];"
                :: "r"(dst), "l"(src), "n"(512), "r"(mbar_base + buf * 8)
                : "memory");
        }
    };

    issue_chunk(0);
    issue_chunk(1);

    float4 acc = make_float4(0.f, 0.f, 0.f, 0.f);
    #pragma unroll
    for (int c = 0; c < CHUNKS; c++) {
        const int buf = c & 1;
        mbar_wait(mbar_base + buf * 8, (c >> 1) & 1);
        #pragma unroll
        for (int k = 0; k < NCHUNK; k++) {
            float  w = __int_as_float(s_wo[warp][c * NCHUNK + k].y);
            float4 v = s_stage[warp][buf][k][lane];
            acc.x = fmaf(w, v.x, acc.x);
            acc.y = fmaf(w, v.y, acc.y);
            acc.z = fmaf(w, v.z, acc.z);
            acc.w = fmaf(w, v.w, acc.w);
        }
        if (c + 2 < CHUNKS) issue_chunk(c + 2);
    }

    out4[b * (GCN_D / 4) + lane] = acc;
}

// ---------------------------------------------------------------------------
extern "C" void kernel_launch(void* const* d_in, const int* in_sizes, int n_in,
                              void* d_out, int out_size) {
    const int*    neigh_cols   = (const int*)d_in[0];
    const int*    unique_ids   = (const int*)d_in[1];
    const float4* embed_table4 = (const float4*)d_in[2];
    float4*       out4         = (float4*)d_out;

    // Zero column degrees via a graph memset node (no dedicated kernel launch).
    void* col_deg_ptr = nullptr;
    cudaGetSymbolAddress(&col_deg_ptr, g_col_deg);
    cudaMemsetAsync(col_deg_ptr, 0, GCN_U * sizeof(int));

    dedupe_degree_kernel<<<GCN_B / 8, 256>>>(neigh_cols);
    aggregate_kernel<<<GCN_B / AGG_ROWS, 32 * AGG_ROWS>>>(
        neigh_cols, unique_ids, embed_table4, out4);
}

// round 10
// speedup vs baseline: 1.2765x; 1.1382x over previous
#include <cuda_runtime.h>
#include <cuda_bf16.h>
#include <math.h>
#include <cstdint>

// Problem constants (GCNAggregator): B=4096, K=32, U=32768, V=100000, D=128
#define GCN_B 4096
#define GCN_K 32
#define GCN_U 32768
#define GCN_D 128
#define AGG_WARPS 8      // rows (warps) per aggregate block

// Scratch (no cudaMalloc allowed)
__device__ int g_col_deg[GCN_U];

// ---------------------------------------------------------------------------
// Kernel 1: per-row dedupe (one warp per row) + column degree accumulation.
// (row mask no longer stored; the aggregate kernel recomputes it locally)
// ---------------------------------------------------------------------------
__global__ void dedupe_degree_kernel(const int* __restrict__ neigh_cols) {
    int warp_in_block = threadIdx.x >> 5;
    int lane = threadIdx.x & 31;
    int b = blockIdx.x * (blockDim.x >> 5) + warp_in_block;

    int c = neigh_cols[b * GCN_K + lane];

    bool first = true;
    #pragma unroll
    for (int j = 0; j < GCN_K; j++) {
        int cj = __shfl_sync(0xFFFFFFFFu, c, j);
        if (j < lane && cj == c) first = false;
    }

    if (first) atomicAdd(&g_col_deg[c], 1);   // spread addresses -> cheap
}

// ---------------------------------------------------------------------------
// Kernel 2: aggregation, dependency-decoupled. One warp per row, lane owns
// 4 consecutive dims (LDG.128 via __ldcg). The gather pipeline launches as
// soon as offsets are known; the weight chain (dedupe shfl + degree load +
// rsqrt) resolves concurrently under the first 8 in-flight gathers and is
// only consumed at FMA time. Duplicates carry w=0 -> branch-free.
// ---------------------------------------------------------------------------
__global__ void __launch_bounds__(32 * AGG_WARPS)
aggregate_kernel(const int* __restrict__ neigh_cols,
                 const int* __restrict__ unique_ids,
                 const float4* __restrict__ embed_table4,  // [V, 32] float4
                 float4* __restrict__ out4) {              // [B, 32] float4
    const int warp = threadIdx.x >> 5;
    const int lane = threadIdx.x & 31;
    const int b    = blockIdx.x * AGG_WARPS + warp;

    __shared__ int   s_off[AGG_WARPS][GCN_K];   // row offsets (float4 units)
    __shared__ float s_w[AGG_WARPS][GCN_K];     // per-neighbor weights

    // ---- step 1: offsets only (shortest possible chain), publish to smem ----
    const int c = neigh_cols[b * GCN_K + lane];
    const int off4 = __ldg(&unique_ids[c]) * (GCN_D / 4);
    s_off[warp][lane] = off4;
    __syncwarp();

    // ---- step 2: launch the gather pipeline immediately ----
    constexpr int P = 8;
    float4 buf[P];
    #pragma unroll
    for (int i = 0; i < P; i++)
        buf[i] = __ldcg(&embed_table4[s_off[warp][i] + lane]);

    // ---- step 3: weight chain resolves under the in-flight gathers ----
    bool first = true;
    #pragma unroll
    for (int j = 0; j < GCN_K; j++) {
        int cj = __shfl_sync(0xFFFFFFFFu, c, j);
        if (j < lane && cj == c) first = false;
    }
    const unsigned mask = __ballot_sync(0xFFFFFFFFu, first);
    float w = 0.0f;
    if (first) {
        int deg = __ldcg(&g_col_deg[c]);          // >= 1 for first occurrences
        w = rsqrtf((float)deg);
    }
    w *= rsqrtf((float)__popc(mask));             // fold row scale into lane weight
    s_w[warp][lane] = w;
    __syncwarp();

    // ---- step 4: rolling FMA + refill ----
    float4 acc = make_float4(0.f, 0.f, 0.f, 0.f);
    #pragma unroll
    for (int k = 0; k < GCN_K; k++) {
        float4 v  = buf[k & (P - 1)];
        float  wk = s_w[warp][k];
        acc.x = fmaf(wk, v.x, acc.x);
        acc.y = fmaf(wk, v.y, acc.y);
        acc.z = fmaf(wk, v.z, acc.z);
        acc.w = fmaf(wk, v.w, acc.w);
        if (k + P < GCN_K)
            buf[k & (P - 1)] = __ldcg(&embed_table4[s_off[warp][k + P] + lane]);
    }

    out4[b * (GCN_D / 4) + lane] = acc;
}

// ---------------------------------------------------------------------------
extern "C" void kernel_launch(void* const* d_in, const int* in_sizes, int n_in,
                              void* d_out, int out_size) {
    const int*    neigh_cols   = (const int*)d_in[0];
    const int*    unique_ids   = (const int*)d_in[1];
    const float4* embed_table4 = (const float4*)d_in[2];
    float4*       out4         = (float4*)d_out;

    // Zero column degrees via a graph memset node (no dedicated kernel launch).
    void* col_deg_ptr = nullptr;
    cudaGetSymbolAddress(&col_deg_ptr, g_col_deg);
    cudaMemsetAsync(col_deg_ptr, 0, GCN_U * sizeof(int));

    dedupe_degree_kernel<<<GCN_B / 8, 256>>>(neigh_cols);
    aggregate_kernel<<<GCN_B / AGG_WARPS, 32 * AGG_WARPS>>>(
        neigh_cols, unique_ids, embed_table4, out4);
}